// round 14
// baseline (speedup 1.0000x reference)
#include <cuda_runtime.h>
#include <cstdint>
#include <cstddef>

#define BB 64
#define TT 512
#define EE 256
#define HH 256
#define LLB 9
#define G4 1024   // 4*H

typedef unsigned long long u64;

// Scratch (device globals; no allocations allowed)
__device__ float g_xg[(size_t)2*TT*G4*BB];   // [dir][t][col][b] 256 MiB
__device__ float g_h [(size_t)2*TT*HH*BB];   // [dir][t][u][b]    64 MiB
__device__ int      g_seqlen[BB];
__device__ unsigned g_barc[512];  // 16 group counters (2 dir x 8 groups), 128B apart

// ---------------- f32x2 helpers ----------------
__device__ __forceinline__ u64 pk2(float x, float y){
    u64 r; asm("mov.b64 %0,{%1,%2};" : "=l"(r) : "f"(x), "f"(y)); return r;
}
__device__ __forceinline__ void upk2(u64 v, float& x, float& y){
    asm("mov.b64 {%0,%1},%2;" : "=f"(x), "=f"(y) : "l"(v));
}
__device__ __forceinline__ u64 fma2(u64 a, u64 b, u64 c){
    u64 d; asm("fma.rn.f32x2 %0,%1,%2,%3;" : "=l"(d) : "l"(a), "l"(b), "l"(c)); return d;
}
__device__ __forceinline__ u64 add2(u64 a, u64 b){
    u64 d; asm("add.rn.f32x2 %0,%1,%2;" : "=l"(d) : "l"(a), "l"(b)); return d;
}

// ---------------- release/acquire primitives ----------------
__device__ __forceinline__ void red_release_add1(unsigned* p){
    asm volatile("red.release.gpu.add.u32 [%0],1;" :: "l"(p) : "memory");
}
__device__ __forceinline__ unsigned ld_acquire(const unsigned* p){
    unsigned v; asm volatile("ld.acquire.gpu.u32 %0,[%1];" : "=r"(v) : "l"(p) : "memory");
    return v;
}

__device__ __forceinline__ float sigf(float x){
    return __fdividef(1.f, 1.f + __expf(-x));
}
__device__ __forceinline__ float tanhfast(float x){
    return 1.f - __fdividef(2.f, __expf(2.f*x) + 1.f);
}

// ---------------------------------------------------------------- seq_len
__global__ void k_seqlen(const int* __restrict__ tokens, float* __restrict__ out_seq){
    int b = blockIdx.x, tid = threadIdx.x;
    int cnt = 0;
    for (int t = tid; t < TT; t += blockDim.x)
        cnt += (tokens[b*TT + t] != 0);
    __shared__ int sred[128];
    sred[tid] = cnt; __syncthreads();
    for (int s = 64; s > 0; s >>= 1){
        if (tid < s) sred[tid] += sred[tid+s];
        __syncthreads();
    }
    if (tid == 0){ g_seqlen[b] = sred[0]; out_seq[b] = (float)sred[0]; }
}

__global__ void k_init(){
    g_barc[threadIdx.x] = 0u;   // 512 threads
}

// ---------------------------------------------------------------- xg GEMM (IDENTICAL to R10/R12 winner)
__global__ void __launch_bounds__(256) k_xg(
    const int* __restrict__ tokens, const float* __restrict__ emb,
    const float* __restrict__ Wxf, const float* __restrict__ bf,
    const float* __restrict__ Wxb, const float* __restrict__ bb_)
{
    extern __shared__ float smf[];
    float* As = smf;                   // [256 k][64 b] f32    64KB
    u64*   Wd = (u64*)(smf + 16384);   // [256 k][64 c] dup   128KB

    int cta  = blockIdx.x;
    int ct   = cta & 31;
    int tch  = cta >> 5;
    int dir  = ct >> 4;
    int col0 = (ct & 15) * 64;
    const float* Wx   = dir ? Wxb : Wxf;
    const float* bias = dir ? bb_ : bf;
    int tid  = threadIdx.x;
    int w    = tid >> 5, lane = tid & 31;
    int cp   = lane & 15, bh = lane >> 4;
    int cg   = w & 1, bg = w >> 1;
    int pb   = bg*8 + bh*4;
    int cb   = cg*32 + cp*2;

    for (int i = tid; i < 4096; i += 256){
        int k = i >> 4, q = i & 15;
        float4 v = *(const float4*)(Wx + (size_t)k*G4 + col0 + q*4);
        Wd[k*64 + q*4 + 0] = pk2(v.x, v.x);
        Wd[k*64 + q*4 + 1] = pk2(v.y, v.y);
        Wd[k*64 + q*4 + 2] = pk2(v.z, v.z);
        Wd[k*64 + q*4 + 3] = pk2(v.w, v.w);
    }
    float bv0 = bias[col0 + cb], bv1 = bias[col0 + cb + 1];
    u64 bini0 = pk2(bv0, bv0), bini1 = pk2(bv1, bv1);

    int gb   = tid & 63;
    int gk16 = (tid >> 6)*16;

    int tbase = tch * 128;
    float4 pf[16];
    {
        int tok = tokens[gb*TT + tbase];
        const float4* row = (const float4*)(emb + (size_t)tok*EE);
        #pragma unroll
        for (int j = 0; j < 16; ++j) pf[j] = row[gk16 + j];
    }

    for (int i = 0; i < 128; ++i){
        int t = tbase + i;
        __syncthreads();
        #pragma unroll
        for (int j = 0; j < 16; ++j){
            int k4 = gk16 + j;
            As[(4*k4+0)*64+gb]=pf[j].x;
            As[(4*k4+1)*64+gb]=pf[j].y;
            As[(4*k4+2)*64+gb]=pf[j].z;
            As[(4*k4+3)*64+gb]=pf[j].w;
        }
        __syncthreads();

        if (i + 1 < 128){
            int tok = tokens[gb*TT + t + 1];
            const float4* row = (const float4*)(emb + (size_t)tok*EE);
            #pragma unroll
            for (int j = 0; j < 16; ++j) pf[j] = row[gk16 + j];
        }

        u64 acc00 = bini0, acc01 = bini0, acc02 = bini0, acc03 = bini0;
        u64 acc10 = bini1, acc11 = bini1, acc12 = bini1, acc13 = bini1;
        const u64* Asu = (const u64*)As;

        #pragma unroll 8
        for (int k = 0; k < 256; ++k){
            ulonglong2 a01 = *(const ulonglong2*)(Asu + k*32 + pb);
            ulonglong2 a23 = *(const ulonglong2*)(Asu + k*32 + pb + 2);
            ulonglong2 wv  = *(const ulonglong2*)(Wd  + k*64 + cb);
            acc00 = fma2(a01.x, wv.x, acc00);
            acc01 = fma2(a01.y, wv.x, acc01);
            acc02 = fma2(a23.x, wv.x, acc02);
            acc03 = fma2(a23.y, wv.x, acc03);
            acc10 = fma2(a01.x, wv.y, acc10);
            acc11 = fma2(a01.y, wv.y, acc11);
            acc12 = fma2(a23.x, wv.y, acc12);
            acc13 = fma2(a23.y, wv.y, acc13);
        }

        u64* dst = (u64*)g_xg + ((size_t)(dir*TT + t)*G4 + col0 + cb)*32 + pb;
        ulonglong2 s;
        s.x = acc00; s.y = acc01; *(ulonglong2*)(dst)          = s;
        s.x = acc02; s.y = acc03; *(ulonglong2*)(dst + 2)      = s;
        s.x = acc10; s.y = acc11; *(ulonglong2*)(dst + 32)     = s;
        s.x = acc12; s.y = acc13; *(ulonglong2*)(dst + 32 + 2) = s;
    }
}

// ---------------------------------------------------------------- recurrence v4
// 128 CTAs: [0,64) fwd, [64,128) bwd. CTA = 4 units x 64 batches.
// 512 threads, 16 warps = 8 k-slices (32 k each) x 2 unit-pairs.
// NO smem h staging: inner loop reads h(t-1) directly from L2/L1 (lines
// shared by 16 warps -> mostly L1 hits). Each warp polls its own group
// counter; W stays in smem (duplicated f32x2 pairs).
__global__ void __launch_bounds__(512) k_recur(
    const float* __restrict__ Whf, const float* __restrict__ Whb)
{
    extern __shared__ u64 smu[];
    u64* wd  = smu;            // [256 k][4 ul][4 g] dup        32KB
    u64* red = smu + 4096;     // 2 x [7 slice][8 j][64 tslot]  56KB

    int cta = blockIdx.x;
    int dir = cta >> 6;
    int u0  = (cta & 63) * 4;
    const float* Wh = dir ? Whb : Whf;
    int tid  = threadIdx.x;
    int w    = tid >> 5, lane = tid & 31;
    int ks   = w >> 1, up = w & 1;        // slice 0..7, pair half
    int uh   = lane >> 4, bp16 = lane & 15;
    int ul   = up*2 + uh;
    int u    = u0 + ul;
    int k0   = ks * 32;
    int tslot = ul*16 + bp16;

    unsigned* gcnt  = &g_barc[(dir*8 + ks)*32];                // slice's producers
    unsigned* myrel = &g_barc[(dir*8 + ((cta & 63) >> 3))*32]; // this CTA's group

    for (int i = tid; i < 4096; i += 512){
        int k = i >> 4, q = i & 15;
        int ulx = q >> 2, g = q & 3;
        float v = Wh[(size_t)k*G4 + g*HH + u0 + ulx];
        wd[k*16 + ulx*4 + g] = pk2(v, v);
    }
    __syncthreads();

    float c0a = 0.f, c1a = 0.f, c0b = 0.f, c1b = 0.f;
    float* hF = g_h + (size_t)dir * TT * HH * BB;
    const u64* xg = (const u64*)g_xg;
    const u64* wrow = wd + k0*16 + ul*4;

    u64 x[8] = {0,0,0,0,0,0,0,0};
    int t0 = dir ? (TT-1) : 0;
    if (ks == 0){
        size_t xb = ((size_t)(dir*TT + t0)*G4 + u)*32 + bp16;
        x[0]=xg[xb];       x[1]=xg[xb+16];
        x[2]=xg[xb+8192];  x[3]=xg[xb+8192+16];
        x[4]=xg[xb+16384]; x[5]=xg[xb+16384+16];
        x[6]=xg[xb+24576]; x[7]=xg[xb+24576+16];
    }

    for (int step = 0; step < TT; ++step){
        int t = dir ? (TT-1-step) : step;
        u64 a0a=x[0], a0b=x[1], a1a=x[2], a1b=x[3];
        u64 a2a=x[4], a2b=x[5], a3a=x[6], a3b=x[7];   // ks>0: zeros

        if (step > 0){
            int tp = dir ? (t+1) : (t-1);
            // every warp polls its slice's producers (converged load)
            unsigned need = 8u * (unsigned)step;
            while (ld_acquire(gcnt) < need) {}

            const u64* hp = (const u64*)(hF + (size_t)tp*HH*BB) + k0*32 + bp16;
            #pragma unroll 8
            for (int kk = 0; kk < 32; ++kk){
                u64 h2a = hp[kk*32];          // LDG, line shared by 16 warps
                u64 h2b = hp[kk*32 + 16];
                ulonglong2 w01 = *(const ulonglong2*)(wrow + kk*16);
                ulonglong2 w23 = *(const ulonglong2*)(wrow + kk*16 + 2);
                a0a = fma2(h2a, w01.x, a0a);  a0b = fma2(h2b, w01.x, a0b);
                a1a = fma2(h2a, w01.y, a1a);  a1b = fma2(h2b, w01.y, a1b);
                a2a = fma2(h2a, w23.x, a2a);  a2b = fma2(h2b, w23.x, a2b);
                a3a = fma2(h2a, w23.y, a3a);  a3b = fma2(h2b, w23.y, a3b);
            }

            u64* redbuf = red + (step & 1)*3584;
            if (ks > 0){
                u64* rp = redbuf + (ks-1)*512 + tslot;   // striped, conflict-free
                rp[0]   = a0a;  rp[64]  = a0b;
                rp[128] = a1a;  rp[192] = a1b;
                rp[256] = a2a;  rp[320] = a2b;
                rp[384] = a3a;  rp[448] = a3b;
            }
            __syncthreads();   // partials visible to ks0

            if (ks == 0){
                #pragma unroll
                for (int s = 0; s < 7; ++s){
                    const u64* rp = redbuf + s*512 + tslot;
                    a0a = add2(a0a, rp[0]);    a0b = add2(a0b, rp[64]);
                    a1a = add2(a1a, rp[128]);  a1b = add2(a1b, rp[192]);
                    a2a = add2(a2a, rp[256]);  a2b = add2(a2b, rp[320]);
                    a3a = add2(a3a, rp[384]);  a3b = add2(a3b, rp[448]);
                }
            }
        }

        if (ks == 0){
            float i0,i1,f0,f1,g0,g1,o0,o1,h0,h1;
            upk2(a0a,i0,i1); upk2(a1a,f0,f1); upk2(a2a,g0,g1); upk2(a3a,o0,o1);
            c0a = sigf(f0)*c0a + sigf(i0)*tanhfast(g0);
            c1a = sigf(f1)*c1a + sigf(i1)*tanhfast(g1);
            h0 = sigf(o0)*tanhfast(c0a);
            h1 = sigf(o1)*tanhfast(c1a);
            *(u64*)(hF + (size_t)t*HH*BB + (size_t)u*BB + 2*bp16) = pk2(h0, h1);

            upk2(a0b,i0,i1); upk2(a1b,f0,f1); upk2(a2b,g0,g1); upk2(a3b,o0,o1);
            c0b = sigf(f0)*c0b + sigf(i0)*tanhfast(g0);
            c1b = sigf(f1)*c1b + sigf(i1)*tanhfast(g1);
            h0 = sigf(o0)*tanhfast(c0b);
            h1 = sigf(o1)*tanhfast(c1b);
            *(u64*)(hF + (size_t)t*HH*BB + (size_t)u*BB + 2*(bp16+16)) = pk2(h0, h1);

            // order both ks0 warps' h stores, then release this CTA's group
            asm volatile("bar.sync 9, 64;" ::: "memory");
            if (tid == 0) red_release_add1(myrel);

            if (step + 1 < TT){   // prefetch next x
                int tn = dir ? (t-1) : (t+1);
                size_t xb = ((size_t)(dir*TT + tn)*G4 + u)*32 + bp16;
                x[0]=xg[xb];       x[1]=xg[xb+16];
                x[2]=xg[xb+8192];  x[3]=xg[xb+8192+16];
                x[4]=xg[xb+16384]; x[5]=xg[xb+16384+16];
                x[6]=xg[xb+24576]; x[7]=xg[xb+24576+16];
            }
        }
    }
}

// ---------------------------------------------------------------- dense
__global__ void __launch_bounds__(576) k_dense(
    const float* __restrict__ Wd, const float* __restrict__ bd,
    float* __restrict__ out)
{
    extern __shared__ float sm[];
    float* hsf = sm;
    float* Wds = sm + 32768;

    int t = blockIdx.x, tid = threadIdx.x;
    const float4* s0 = (const float4*)(g_h + (size_t)t*HH*BB);
    const float4* s1 = (const float4*)(g_h + (size_t)(TT + t)*HH*BB);
    float4* d0 = (float4*)hsf;
    for (int i = tid; i < 4096; i += 576) d0[i] = s0[i];
    for (int i = tid; i < 4096; i += 576) d0[4096 + i] = s1[i];
    for (int i = tid; i < 512*LLB; i += 576) Wds[i] = Wd[i];
    __syncthreads();

    int b = tid / LLB;
    int l = tid - b*LLB;
    float acc = bd[l];
    #pragma unroll 4
    for (int k = 0; k < 256; ++k)
        acc += hsf[k*64 + b] * Wds[k*LLB + l];
    #pragma unroll 4
    for (int k = 0; k < 256; ++k)
        acc += hsf[16384 + k*64 + b] * Wds[(256+k)*LLB + l];
    out[((size_t)b*TT + t)*LLB + l] = acc;
}

// ---------------------------------------------------------------- CRF
__global__ void k_crf(const int* __restrict__ labels, const float* __restrict__ trans,
                      const float* __restrict__ logits, float* __restrict__ out_ll)
{
    int b = blockIdx.x;
    int j = threadIdx.x;
    int sl = g_seqlen[b];
    const float* lg = logits + (size_t)b*TT*LLB;
    const int*   tg = labels + (size_t)b*TT;

    float sc = 0.f;
    for (int t = j; t < TT; t += 32){
        if (t < sl){
            sc += lg[t*LLB + tg[t]];
            if (t >= 1) sc += trans[tg[t-1]*LLB + tg[t]];
        }
    }
    #pragma unroll
    for (int o = 16; o > 0; o >>= 1) sc += __shfl_xor_sync(0xffffffffu, sc, o);

    float trj[9];
    if (j < 9){
        #pragma unroll
        for (int i = 0; i < 9; ++i) trj[i] = trans[i*LLB + j];
    }
    float a[9];
    #pragma unroll
    for (int i = 0; i < 9; ++i) a[i] = lg[i];

    __shared__ float sa[9];
    int tmax = (sl < TT) ? sl : TT;
    for (int t = 1; t < tmax; ++t){
        if (j < 9){
            float lgt = lg[t*LLB + j];
            float v[9]; float m = -1e30f;
            #pragma unroll
            for (int i = 0; i < 9; ++i){ v[i] = a[i] + trj[i]; m = fmaxf(m, v[i]); }
            float s = 0.f;
            #pragma unroll
            for (int i = 0; i < 9; ++i) s += __expf(v[i] - m);
            sa[j] = m + __logf(s) + lgt;
        }
        __syncwarp();
        #pragma unroll
        for (int i = 0; i < 9; ++i) a[i] = sa[i];
        __syncwarp();
    }

    if (j == 0){
        float m = a[0];
        #pragma unroll
        for (int i = 1; i < 9; ++i) m = fmaxf(m, a[i]);
        float s = 0.f;
        #pragma unroll
        for (int i = 0; i < 9; ++i) s += __expf(a[i] - m);
        out_ll[b] = sc - (m + __logf(s));
    }
}

// ---------------------------------------------------------------- launch
extern "C" void kernel_launch(void* const* d_in, const int* in_sizes, int n_in,
                              void* d_out, int out_size)
{
    const int*   tokens = (const int*)  d_in[0];
    const int*   labels = (const int*)  d_in[1];
    const float* emb    = (const float*)d_in[2];
    const float* Wxf    = (const float*)d_in[3];
    const float* Whf    = (const float*)d_in[4];
    const float* bf     = (const float*)d_in[5];
    const float* Wxb    = (const float*)d_in[6];
    const float* Whb    = (const float*)d_in[7];
    const float* bb     = (const float*)d_in[8];
    const float* Wd     = (const float*)d_in[9];
    const float* bd     = (const float*)d_in[10];
    const float* trans  = (const float*)d_in[11];
    float* out = (float*)d_out;

    cudaFuncSetAttribute(k_xg,    cudaFuncAttributeMaxDynamicSharedMemorySize, 196608);
    cudaFuncSetAttribute(k_recur, cudaFuncAttributeMaxDynamicSharedMemorySize, 90112);
    cudaFuncSetAttribute(k_dense, cudaFuncAttributeMaxDynamicSharedMemorySize, 149504);

    const int LOGITS_N = BB*TT*LLB;   // 294912

    k_init<<<1, 512>>>();
    k_seqlen<<<BB, 128>>>(tokens, out + LOGITS_N);

    k_xg<<<128, 256, 196608>>>(tokens, emb, Wxf, bf, Wxb, bb);

    // launch #4 -> ncu-profiled slot
    k_recur<<<128, 512, 90112>>>(Whf, Whb);

    k_dense<<<TT, 576, 149504>>>(Wd, bd, out);

    k_crf<<<BB, 32>>>(labels, trans, out, out + LOGITS_N + BB);
}

// round 15
// speedup vs baseline: 1.2153x; 1.2153x over previous
#include <cuda_runtime.h>
#include <cstdint>
#include <cstddef>

#define BB 64
#define TT 512
#define EE 256
#define HH 256
#define LLB 9
#define G4 1024   // 4*H

typedef unsigned long long u64;

// Scratch (device globals; no allocations allowed)
__device__ float g_xg[(size_t)2*TT*G4*BB];   // [dir][t][col][b] 256 MiB
__device__ float g_h [(size_t)2*TT*HH*BB];   // [dir][t][u][b]    64 MiB
__device__ int      g_seqlen[BB];
__device__ unsigned g_barc[512];  // 16 group counters (2 dir x 8 groups), 128B apart

// ---------------- f32x2 helpers ----------------
__device__ __forceinline__ u64 pk2(float x, float y){
    u64 r; asm("mov.b64 %0,{%1,%2};" : "=l"(r) : "f"(x), "f"(y)); return r;
}
__device__ __forceinline__ void upk2(u64 v, float& x, float& y){
    asm("mov.b64 {%0,%1},%2;" : "=f"(x), "=f"(y) : "l"(v));
}
__device__ __forceinline__ u64 fma2(u64 a, u64 b, u64 c){
    u64 d; asm("fma.rn.f32x2 %0,%1,%2,%3;" : "=l"(d) : "l"(a), "l"(b), "l"(c)); return d;
}
__device__ __forceinline__ u64 add2(u64 a, u64 b){
    u64 d; asm("add.rn.f32x2 %0,%1,%2;" : "=l"(d) : "l"(a), "l"(b)); return d;
}

// ---------------- release/acquire primitives ----------------
__device__ __forceinline__ void red_release_add1(unsigned* p){
    asm volatile("red.release.gpu.add.u32 [%0],1;" :: "l"(p) : "memory");
}
__device__ __forceinline__ unsigned ld_acquire(const unsigned* p){
    unsigned v; asm volatile("ld.acquire.gpu.u32 %0,[%1];" : "=r"(v) : "l"(p) : "memory");
    return v;
}

__device__ __forceinline__ float sigf(float x){
    return __fdividef(1.f, 1.f + __expf(-x));
}
__device__ __forceinline__ float tanhfast(float x){
    return 1.f - __fdividef(2.f, __expf(2.f*x) + 1.f);
}

// ---------------------------------------------------------------- seq_len
__global__ void k_seqlen(const int* __restrict__ tokens, float* __restrict__ out_seq){
    int b = blockIdx.x, tid = threadIdx.x;
    int cnt = 0;
    for (int t = tid; t < TT; t += blockDim.x)
        cnt += (tokens[b*TT + t] != 0);
    __shared__ int sred[128];
    sred[tid] = cnt; __syncthreads();
    for (int s = 64; s > 0; s >>= 1){
        if (tid < s) sred[tid] += sred[tid+s];
        __syncthreads();
    }
    if (tid == 0){ g_seqlen[b] = sred[0]; out_seq[b] = (float)sred[0]; }
}

__global__ void k_init(){
    g_barc[threadIdx.x] = 0u;   // 512 threads
}

// ---------------------------------------------------------------- xg GEMM (IDENTICAL to R10/R12 winner)
__global__ void __launch_bounds__(256) k_xg(
    const int* __restrict__ tokens, const float* __restrict__ emb,
    const float* __restrict__ Wxf, const float* __restrict__ bf,
    const float* __restrict__ Wxb, const float* __restrict__ bb_)
{
    extern __shared__ float smf[];
    float* As = smf;                   // [256 k][64 b] f32    64KB
    u64*   Wd = (u64*)(smf + 16384);   // [256 k][64 c] dup   128KB

    int cta  = blockIdx.x;
    int ct   = cta & 31;
    int tch  = cta >> 5;
    int dir  = ct >> 4;
    int col0 = (ct & 15) * 64;
    const float* Wx   = dir ? Wxb : Wxf;
    const float* bias = dir ? bb_ : bf;
    int tid  = threadIdx.x;
    int w    = tid >> 5, lane = tid & 31;
    int cp   = lane & 15, bh = lane >> 4;
    int cg   = w & 1, bg = w >> 1;
    int pb   = bg*8 + bh*4;
    int cb   = cg*32 + cp*2;

    for (int i = tid; i < 4096; i += 256){
        int k = i >> 4, q = i & 15;
        float4 v = *(const float4*)(Wx + (size_t)k*G4 + col0 + q*4);
        Wd[k*64 + q*4 + 0] = pk2(v.x, v.x);
        Wd[k*64 + q*4 + 1] = pk2(v.y, v.y);
        Wd[k*64 + q*4 + 2] = pk2(v.z, v.z);
        Wd[k*64 + q*4 + 3] = pk2(v.w, v.w);
    }
    float bv0 = bias[col0 + cb], bv1 = bias[col0 + cb + 1];
    u64 bini0 = pk2(bv0, bv0), bini1 = pk2(bv1, bv1);

    int gb   = tid & 63;
    int gk16 = (tid >> 6)*16;

    int tbase = tch * 128;
    float4 pf[16];
    {
        int tok = tokens[gb*TT + tbase];
        const float4* row = (const float4*)(emb + (size_t)tok*EE);
        #pragma unroll
        for (int j = 0; j < 16; ++j) pf[j] = row[gk16 + j];
    }

    for (int i = 0; i < 128; ++i){
        int t = tbase + i;
        __syncthreads();
        #pragma unroll
        for (int j = 0; j < 16; ++j){
            int k4 = gk16 + j;
            As[(4*k4+0)*64+gb]=pf[j].x;
            As[(4*k4+1)*64+gb]=pf[j].y;
            As[(4*k4+2)*64+gb]=pf[j].z;
            As[(4*k4+3)*64+gb]=pf[j].w;
        }
        __syncthreads();

        if (i + 1 < 128){
            int tok = tokens[gb*TT + t + 1];
            const float4* row = (const float4*)(emb + (size_t)tok*EE);
            #pragma unroll
            for (int j = 0; j < 16; ++j) pf[j] = row[gk16 + j];
        }

        u64 acc00 = bini0, acc01 = bini0, acc02 = bini0, acc03 = bini0;
        u64 acc10 = bini1, acc11 = bini1, acc12 = bini1, acc13 = bini1;
        const u64* Asu = (const u64*)As;

        #pragma unroll 8
        for (int k = 0; k < 256; ++k){
            ulonglong2 a01 = *(const ulonglong2*)(Asu + k*32 + pb);
            ulonglong2 a23 = *(const ulonglong2*)(Asu + k*32 + pb + 2);
            ulonglong2 wv  = *(const ulonglong2*)(Wd  + k*64 + cb);
            acc00 = fma2(a01.x, wv.x, acc00);
            acc01 = fma2(a01.y, wv.x, acc01);
            acc02 = fma2(a23.x, wv.x, acc02);
            acc03 = fma2(a23.y, wv.x, acc03);
            acc10 = fma2(a01.x, wv.y, acc10);
            acc11 = fma2(a01.y, wv.y, acc11);
            acc12 = fma2(a23.x, wv.y, acc12);
            acc13 = fma2(a23.y, wv.y, acc13);
        }

        u64* dst = (u64*)g_xg + ((size_t)(dir*TT + t)*G4 + col0 + cb)*32 + pb;
        ulonglong2 s;
        s.x = acc00; s.y = acc01; *(ulonglong2*)(dst)          = s;
        s.x = acc02; s.y = acc03; *(ulonglong2*)(dst + 2)      = s;
        s.x = acc10; s.y = acc11; *(ulonglong2*)(dst + 32)     = s;
        s.x = acc12; s.y = acc13; *(ulonglong2*)(dst + 32 + 2) = s;
    }
}

// ---------------------------------------------------------------- recurrence v5 (= R13 + pair-split h copy)
// 128 CTAs: [0,64) fwd, [64,128) bwd. CTA = 4 units x 64 batches.
// 512 threads, 16 warps = 8 k-slices (32 k each) x 2 unit-pairs.
// Slice-local sync: both warps of a slice poll the slice's group counter,
// then EACH copies half (8 x 256B) of the slice's h_prev into smem.
__global__ void __launch_bounds__(512) k_recur(
    const float* __restrict__ Whf, const float* __restrict__ Whb)
{
    extern __shared__ u64 smu[];
    u64* hs  = smu;            // [256 k][32 bp]                64KB
    u64* wd  = smu + 8192;     // [256 k][4 ul][4 g] dup        32KB
    u64* red = smu + 12288;    // 2 x [7 slice][8 j][64 tslot]  56KB

    int cta = blockIdx.x;
    int dir = cta >> 6;
    int u0  = (cta & 63) * 4;
    const float* Wh = dir ? Whb : Whf;
    int tid  = threadIdx.x;
    int w    = tid >> 5, lane = tid & 31;
    int ks   = w >> 1, up = w & 1;        // slice 0..7, pair half
    int uh   = lane >> 4, bp16 = lane & 15;
    int ul   = up*2 + uh;
    int u    = u0 + ul;
    int k0   = ks * 32;
    int tslot = ul*16 + bp16;

    unsigned* gcnt  = &g_barc[(dir*8 + ks)*32];                // slice's producers
    unsigned* myrel = &g_barc[(dir*8 + ((cta & 63) >> 3))*32]; // this CTA's group

    for (int i = tid; i < 4096; i += 512){
        int k = i >> 4, q = i & 15;
        int ulx = q >> 2, g = q & 3;
        float v = Wh[(size_t)k*G4 + g*HH + u0 + ulx];
        wd[k*16 + ulx*4 + g] = pk2(v, v);
    }
    __syncthreads();

    float c0a = 0.f, c1a = 0.f, c0b = 0.f, c1b = 0.f;
    float* hF = g_h + (size_t)dir * TT * HH * BB;
    const u64* xg = (const u64*)g_xg;
    const u64* wrow = wd + k0*16 + ul*4;
    const u64* hrow = hs + k0*32 + bp16;

    u64 x[8] = {0,0,0,0,0,0,0,0};
    int t0 = dir ? (TT-1) : 0;
    if (ks == 0){
        size_t xb = ((size_t)(dir*TT + t0)*G4 + u)*32 + bp16;
        x[0]=xg[xb];       x[1]=xg[xb+16];
        x[2]=xg[xb+8192];  x[3]=xg[xb+8192+16];
        x[4]=xg[xb+16384]; x[5]=xg[xb+16384+16];
        x[6]=xg[xb+24576]; x[7]=xg[xb+24576+16];
    }

    for (int step = 0; step < TT; ++step){
        int t = dir ? (TT-1-step) : step;
        u64 a0a=x[0], a0b=x[1], a1a=x[2], a1b=x[3];
        u64 a2a=x[4], a2b=x[5], a3a=x[6], a3b=x[7];   // ks>0: zeros

        if (step > 0){
            int tp = dir ? (t+1) : (t-1);
            // BOTH warps of the slice poll (converged load), then split the copy:
            // up0 copies rows 0..7, up1 copies rows 8..15 of the slice's 16 rows.
            {
                unsigned need = 8u * (unsigned)step;
                while (ld_acquire(gcnt) < need) {}
                const ulonglong2* src = (const ulonglong2*)(hF + (size_t)tp*HH*BB);
                ulonglong2* dst = (ulonglong2*)hs;
                int base = ks*512 + up*256;
                #pragma unroll
                for (int jj = 0; jj < 8; ++jj)
                    dst[base + jj*32 + lane] = src[base + jj*32 + lane];
            }
            asm volatile("bar.sync %0, %1;" :: "r"(ks+1), "r"(64) : "memory");

            #pragma unroll 8
            for (int kk = 0; kk < 32; ++kk){
                u64 h2a = hrow[kk*32];
                u64 h2b = hrow[kk*32 + 16];
                ulonglong2 w01 = *(const ulonglong2*)(wrow + kk*16);
                ulonglong2 w23 = *(const ulonglong2*)(wrow + kk*16 + 2);
                a0a = fma2(h2a, w01.x, a0a);  a0b = fma2(h2b, w01.x, a0b);
                a1a = fma2(h2a, w01.y, a1a);  a1b = fma2(h2b, w01.y, a1b);
                a2a = fma2(h2a, w23.x, a2a);  a2b = fma2(h2b, w23.x, a2b);
                a3a = fma2(h2a, w23.y, a3a);  a3b = fma2(h2b, w23.y, a3b);
            }

            u64* redbuf = red + (step & 1)*3584;
            if (ks > 0){
                u64* rp = redbuf + (ks-1)*512 + tslot;   // striped, conflict-free
                rp[0]   = a0a;  rp[64]  = a0b;
                rp[128] = a1a;  rp[192] = a1b;
                rp[256] = a2a;  rp[320] = a2b;
                rp[384] = a3a;  rp[448] = a3b;
            }
            __syncthreads();   // partials visible to ks0

            if (ks == 0){
                #pragma unroll
                for (int s = 0; s < 7; ++s){
                    const u64* rp = redbuf + s*512 + tslot;
                    a0a = add2(a0a, rp[0]);    a0b = add2(a0b, rp[64]);
                    a1a = add2(a1a, rp[128]);  a1b = add2(a1b, rp[192]);
                    a2a = add2(a2a, rp[256]);  a2b = add2(a2b, rp[320]);
                    a3a = add2(a3a, rp[384]);  a3b = add2(a3b, rp[448]);
                }
            }
        }

        if (ks == 0){
            float i0,i1,f0,f1,g0,g1,o0,o1,h0,h1;
            upk2(a0a,i0,i1); upk2(a1a,f0,f1); upk2(a2a,g0,g1); upk2(a3a,o0,o1);
            c0a = sigf(f0)*c0a + sigf(i0)*tanhfast(g0);
            c1a = sigf(f1)*c1a + sigf(i1)*tanhfast(g1);
            h0 = sigf(o0)*tanhfast(c0a);
            h1 = sigf(o1)*tanhfast(c1a);
            *(u64*)(hF + (size_t)t*HH*BB + (size_t)u*BB + 2*bp16) = pk2(h0, h1);

            upk2(a0b,i0,i1); upk2(a1b,f0,f1); upk2(a2b,g0,g1); upk2(a3b,o0,o1);
            c0b = sigf(f0)*c0b + sigf(i0)*tanhfast(g0);
            c1b = sigf(f1)*c1b + sigf(i1)*tanhfast(g1);
            h0 = sigf(o0)*tanhfast(c0b);
            h1 = sigf(o1)*tanhfast(c1b);
            *(u64*)(hF + (size_t)t*HH*BB + (size_t)u*BB + 2*(bp16+16)) = pk2(h0, h1);

            // order both ks0 warps' h stores, then release this CTA's group
            asm volatile("bar.sync 9, 64;" ::: "memory");
            if (tid == 0) red_release_add1(myrel);

            if (step + 1 < TT){   // prefetch next x
                int tn = dir ? (t-1) : (t+1);
                size_t xb = ((size_t)(dir*TT + tn)*G4 + u)*32 + bp16;
                x[0]=xg[xb];       x[1]=xg[xb+16];
                x[2]=xg[xb+8192];  x[3]=xg[xb+8192+16];
                x[4]=xg[xb+16384]; x[5]=xg[xb+16384+16];
                x[6]=xg[xb+24576]; x[7]=xg[xb+24576+16];
            }
        }
    }
}

// ---------------------------------------------------------------- dense
__global__ void __launch_bounds__(576) k_dense(
    const float* __restrict__ Wd, const float* __restrict__ bd,
    float* __restrict__ out)
{
    extern __shared__ float sm[];
    float* hsf = sm;
    float* Wds = sm + 32768;

    int t = blockIdx.x, tid = threadIdx.x;
    const float4* s0 = (const float4*)(g_h + (size_t)t*HH*BB);
    const float4* s1 = (const float4*)(g_h + (size_t)(TT + t)*HH*BB);
    float4* d0 = (float4*)hsf;
    for (int i = tid; i < 4096; i += 576) d0[i] = s0[i];
    for (int i = tid; i < 4096; i += 576) d0[4096 + i] = s1[i];
    for (int i = tid; i < 512*LLB; i += 576) Wds[i] = Wd[i];
    __syncthreads();

    int b = tid / LLB;
    int l = tid - b*LLB;
    float acc = bd[l];
    #pragma unroll 4
    for (int k = 0; k < 256; ++k)
        acc += hsf[k*64 + b] * Wds[k*LLB + l];
    #pragma unroll 4
    for (int k = 0; k < 256; ++k)
        acc += hsf[16384 + k*64 + b] * Wds[(256+k)*LLB + l];
    out[((size_t)b*TT + t)*LLB + l] = acc;
}

// ---------------------------------------------------------------- CRF
__global__ void k_crf(const int* __restrict__ labels, const float* __restrict__ trans,
                      const float* __restrict__ logits, float* __restrict__ out_ll)
{
    int b = blockIdx.x;
    int j = threadIdx.x;
    int sl = g_seqlen[b];
    const float* lg = logits + (size_t)b*TT*LLB;
    const int*   tg = labels + (size_t)b*TT;

    float sc = 0.f;
    for (int t = j; t < TT; t += 32){
        if (t < sl){
            sc += lg[t*LLB + tg[t]];
            if (t >= 1) sc += trans[tg[t-1]*LLB + tg[t]];
        }
    }
    #pragma unroll
    for (int o = 16; o > 0; o >>= 1) sc += __shfl_xor_sync(0xffffffffu, sc, o);

    float trj[9];
    if (j < 9){
        #pragma unroll
        for (int i = 0; i < 9; ++i) trj[i] = trans[i*LLB + j];
    }
    float a[9];
    #pragma unroll
    for (int i = 0; i < 9; ++i) a[i] = lg[i];

    __shared__ float sa[9];
    int tmax = (sl < TT) ? sl : TT;
    for (int t = 1; t < tmax; ++t){
        if (j < 9){
            float lgt = lg[t*LLB + j];
            float v[9]; float m = -1e30f;
            #pragma unroll
            for (int i = 0; i < 9; ++i){ v[i] = a[i] + trj[i]; m = fmaxf(m, v[i]); }
            float s = 0.f;
            #pragma unroll
            for (int i = 0; i < 9; ++i) s += __expf(v[i] - m);
            sa[j] = m + __logf(s) + lgt;
        }
        __syncwarp();
        #pragma unroll
        for (int i = 0; i < 9; ++i) a[i] = sa[i];
        __syncwarp();
    }

    if (j == 0){
        float m = a[0];
        #pragma unroll
        for (int i = 1; i < 9; ++i) m = fmaxf(m, a[i]);
        float s = 0.f;
        #pragma unroll
        for (int i = 0; i < 9; ++i) s += __expf(a[i] - m);
        out_ll[b] = sc - (m + __logf(s));
    }
}

// ---------------------------------------------------------------- launch
extern "C" void kernel_launch(void* const* d_in, const int* in_sizes, int n_in,
                              void* d_out, int out_size)
{
    const int*   tokens = (const int*)  d_in[0];
    const int*   labels = (const int*)  d_in[1];
    const float* emb    = (const float*)d_in[2];
    const float* Wxf    = (const float*)d_in[3];
    const float* Whf    = (const float*)d_in[4];
    const float* bf     = (const float*)d_in[5];
    const float* Wxb    = (const float*)d_in[6];
    const float* Whb    = (const float*)d_in[7];
    const float* bb     = (const float*)d_in[8];
    const float* Wd     = (const float*)d_in[9];
    const float* bd     = (const float*)d_in[10];
    const float* trans  = (const float*)d_in[11];
    float* out = (float*)d_out;

    cudaFuncSetAttribute(k_xg,    cudaFuncAttributeMaxDynamicSharedMemorySize, 196608);
    cudaFuncSetAttribute(k_recur, cudaFuncAttributeMaxDynamicSharedMemorySize, 155648);
    cudaFuncSetAttribute(k_dense, cudaFuncAttributeMaxDynamicSharedMemorySize, 149504);

    const int LOGITS_N = BB*TT*LLB;   // 294912

    k_init<<<1, 512>>>();
    k_seqlen<<<BB, 128>>>(tokens, out + LOGITS_N);

    k_xg<<<128, 256, 196608>>>(tokens, emb, Wxf, bf, Wxb, bb);

    // launch #4 -> ncu-profiled slot
    k_recur<<<128, 512, 155648>>>(Whf, Whb);

    k_dense<<<TT, 576, 149504>>>(Wd, bd, out);

    k_crf<<<BB, 32>>>(labels, trans, out, out + LOGITS_N + BB);
}